// round 13
// baseline (speedup 1.0000x reference)
#include <cuda_runtime.h>

#define HID    32
#define EMB    32
#define BD     32
#define VOCABN 50257
#define S_SRC  64
#define NSTEP  63
#define GSZ    (4*HID)     // 128 gate rows per layer
#define NB     296         // 2 blocks per SM
#define RPB    170         // vocab rows per block: 296*170 = 50320 >= 50257

// ---------------- device scratch ----------------
__device__ __align__(16) float g_h1T[HID*BD];          // [k][b]
__device__ unsigned long long g_amax3[3][BD];          // triple-buffered per-batch argmax
__device__ unsigned g_hflag[BD];                       // per-batch h1-ready (monotonic)
__device__ unsigned g_arr2;                            // arrival counter (monotonic)
__device__ unsigned g_arriveB, g_relB;                 // init barrier

// ---------------- helpers ----------------
__device__ __forceinline__ float sigf(float x){ return 1.f/(1.f+expf(-x)); }

__device__ __forceinline__ unsigned long long pk2(float lo, float hi){
    unsigned long long r;
    asm("mov.b64 %0, {%1, %2};" : "=l"(r) : "f"(lo), "f"(hi));
    return r;
}
__device__ __forceinline__ unsigned long long ffma2(unsigned long long a,
                                                    unsigned long long b,
                                                    unsigned long long c){
    unsigned long long d;
    asm("fma.rn.f32x2 %0, %1, %2, %3;" : "=l"(d) : "l"(a), "l"(b), "l"(c));
    return d;
}
__device__ __forceinline__ unsigned ordb(unsigned u){
    return (u & 0x80000000u) ? ~u : (u | 0x80000000u);
}

// ================= the one persistent kernel =================
__global__ void __launch_bounds__(256, 2) mega_kernel(
    const int* __restrict__ x_src, const int* __restrict__ x_tgt,
    const float* __restrict__ enc_emb,
    const float* __restrict__ eWih0, const float* __restrict__ eWhh0,
    const float* __restrict__ ebih0, const float* __restrict__ ebhh0,
    const float* __restrict__ eWih1, const float* __restrict__ eWhh1,
    const float* __restrict__ ebih1, const float* __restrict__ ebhh1,
    const float* __restrict__ dec_emb,
    const float* __restrict__ dWih0, const float* __restrict__ dWhh0,
    const float* __restrict__ dbih0, const float* __restrict__ dbhh0,
    const float* __restrict__ dWih1, const float* __restrict__ dWhh1,
    const float* __restrict__ dbih1, const float* __restrict__ dbhh1,
    const float* __restrict__ fcW,   const float* __restrict__ fcb,
    float* __restrict__ out)
{
    const int bid = blockIdx.x, tid = threadIdx.x;
    __shared__ float xs[EMB], h0s[HID], c0s[HID], h1s[HID], c1s[HID];
    __shared__ float gs[2*GSZ];
    __shared__ __align__(16) unsigned long long hp[HID*16];
    __shared__ unsigned long long cand[256];
    __shared__ int toks;

    // base snapshots (all counters monotonic across graph replays)
    const unsigned baseH = *(volatile unsigned*)&g_hflag[0];
    const unsigned baseC = *(volatile unsigned*)&g_arr2;
    const unsigned baseB = *(volatile unsigned*)&g_relB;

    // ---- initial full grid barrier (replay-safe) ----
    __syncthreads();
    if (tid == 0){
        __threadfence();
        if (atomicAdd(&g_arriveB, 1u) == NB-1u){
            atomicExch(&g_arriveB, 0u);
            __threadfence();
            atomicExch(&g_relB, baseB + 1u);
        } else {
            while ((int)(*(volatile unsigned*)&g_relB - (baseB + 1u)) < 0) {}
        }
    }
    __syncthreads();

    float hpart = 0.f;   // precomputed Whh·h contribution for next cell

    // ================= encoder (blocks 0..31, one batch each) =================
    if (bid < BD){
        float wi[HID], wh[HID], bias2;
        if (tid < GSZ){
            #pragma unroll
            for (int k=0;k<HID;k++){ wi[k]=eWih0[tid*EMB+k]; wh[k]=eWhh0[tid*HID+k]; }
            bias2 = ebih0[tid] + ebhh0[tid];
        } else {
            const int j = tid - GSZ;
            #pragma unroll
            for (int k=0;k<HID;k++){ wi[k]=eWih1[j*HID+k]; wh[k]=eWhh1[j*HID+k]; }
            bias2 = ebih1[j] + ebhh1[j];
        }
        if (tid < HID){ h0s[tid]=0.f; c0s[tid]=0.f; h1s[tid]=0.f; c1s[tid]=0.f; }
        __syncthreads();

        for (int s=0;s<S_SRC;s++){
            if (tid < EMB) xs[tid] = enc_emb[(size_t)x_src[s*BD+bid]*EMB + tid];
            __syncthreads();
            if (tid < GSZ){
                float a0=bias2, a1=0.f, a2=0.f, a3=0.f;
                #pragma unroll
                for (int k=0;k<HID;k+=4){
                    a0=fmaf(xs[k],wi[k],a0);     a1=fmaf(xs[k+1],wi[k+1],a1);
                    a2=fmaf(xs[k+2],wi[k+2],a2); a3=fmaf(xs[k+3],wi[k+3],a3);
                }
                #pragma unroll
                for (int k=0;k<HID;k+=4){
                    a0=fmaf(h0s[k],wh[k],a0);     a1=fmaf(h0s[k+1],wh[k+1],a1);
                    a2=fmaf(h0s[k+2],wh[k+2],a2); a3=fmaf(h0s[k+3],wh[k+3],a3);
                }
                gs[tid] = (a0+a1)+(a2+a3);
            }
            __syncthreads();
            if (tid < HID){
                float ig=sigf(gs[tid]),        fg=sigf(gs[HID+tid]);
                float gg=tanhf(gs[2*HID+tid]), og=sigf(gs[3*HID+tid]);
                float c2 = fg*c0s[tid] + ig*gg;
                c0s[tid]=c2; h0s[tid]=og*tanhf(c2);
            }
            __syncthreads();
            if (tid >= GSZ){
                float a0=bias2, a1=0.f, a2=0.f, a3=0.f;
                #pragma unroll
                for (int k=0;k<HID;k+=4){
                    a0=fmaf(h0s[k],wi[k],a0);     a1=fmaf(h0s[k+1],wi[k+1],a1);
                    a2=fmaf(h0s[k+2],wi[k+2],a2); a3=fmaf(h0s[k+3],wi[k+3],a3);
                }
                #pragma unroll
                for (int k=0;k<HID;k+=4){
                    a0=fmaf(h1s[k],wh[k],a0);     a1=fmaf(h1s[k+1],wh[k+1],a1);
                    a2=fmaf(h1s[k+2],wh[k+2],a2); a3=fmaf(h1s[k+3],wh[k+3],a3);
                }
                gs[GSZ + (tid-GSZ)] = (a0+a1)+(a2+a3);
            }
            __syncthreads();
            if (tid < HID){
                float ig=sigf(gs[GSZ+tid]),        fg=sigf(gs[GSZ+HID+tid]);
                float gg=tanhf(gs[GSZ+2*HID+tid]), og=sigf(gs[GSZ+3*HID+tid]);
                float c2 = fg*c1s[tid] + ig*gg;
                c1s[tid]=c2; h1s[tid]=og*tanhf(c2);
            }
            __syncthreads();
        }
        // precompute Whh·h for cell(0)
        if (tid < GSZ){
            float a0=0.f,a1=0.f,a2=0.f,a3=0.f;
            const float4* wh4 = (const float4*)(dWhh0 + tid*HID);
            #pragma unroll
            for (int q=0;q<8;q++){
                float4 ww = wh4[q];
                a0=fmaf(h0s[4*q],ww.x,a0);   a1=fmaf(h0s[4*q+1],ww.y,a1);
                a2=fmaf(h0s[4*q+2],ww.z,a2); a3=fmaf(h0s[4*q+3],ww.w,a3);
            }
            hpart = (a0+a1)+(a2+a3);
        } else {
            float a0=0.f,a1=0.f,a2=0.f,a3=0.f;
            const float4* wh4 = (const float4*)(dWhh1 + (tid-GSZ)*HID);
            #pragma unroll
            for (int q=0;q<8;q++){
                float4 ww = wh4[q];
                a0=fmaf(h1s[4*q],ww.x,a0);   a1=fmaf(h1s[4*q+1],ww.y,a1);
                a2=fmaf(h1s[4*q+2],ww.z,a2); a3=fmaf(h1s[4*q+3],ww.w,a3);
            }
            hpart = (a0+a1)+(a2+a3);
        }
    }

    // ================= persistent fc weights, warp-balanced row mapping =================
    const int sel  = (bid >= NB/2) ? 1 : 0;
    const int w8   = tid >> 5, lane = tid & 31;
    const bool wact = sel ? ((w8 < 4) || (w8 >= 6)) : (w8 < 6);
    const int wslot = sel ? ((w8 < 4) ? w8 : (w8 - 2)) : w8;
    const int j    = wslot*32 + lane;                 // 0..191
    const int v    = bid*RPB + j;
    const bool valid = wact && (j < RPB) && (v < VOCABN);
    const int vc   = valid ? v : (VOCABN-1);

    float w[HID];
    {
        const float4* w4 = (const float4*)(fcW + (size_t)vc*HID);
        #pragma unroll
        for (int q=0;q<8;q++){
            float4 t4 = w4[q];
            w[4*q]=t4.x; w[4*q+1]=t4.y; w[4*q+2]=t4.z; w[4*q+3]=t4.w;
        }
    }
    const float bias = fcb[vc];

    // ================= decoder loop =================
    for (int t=0;t<NSTEP;t++){
        // ---------- cell (blocks 0..31) ----------
        if (bid < BD){
            if (tid == 0){
                if (t == 0) toks = x_tgt[bid];
                else {
                    const unsigned tgt = baseC + (unsigned)NB*(unsigned)t;
                    while ((int)(*(volatile unsigned*)&g_arr2 - tgt) < 0) {}
                    __threadfence();
                    volatile unsigned long long* slot = &g_amax3[(t-1)%3][bid];
                    unsigned long long k = *slot;
                    *slot = 0ull;                      // re-arm (triple-buffered)
                    toks = (int)(0xFFFFFFFFu - (unsigned)(k & 0xFFFFFFFFull));
                }
            }
            __syncthreads();
            if (tid < EMB) xs[tid] = dec_emb[(size_t)toks*EMB + tid];
            __syncthreads();

            if (tid < GSZ){
                float a0 = dbih0[tid]+dbhh0[tid]+hpart, a1=0.f, a2=0.f, a3=0.f;
                const float4* wi4 = (const float4*)(dWih0 + tid*EMB);
                #pragma unroll
                for (int q=0;q<8;q++){
                    float4 ww = wi4[q];
                    a0=fmaf(xs[4*q],ww.x,a0);   a1=fmaf(xs[4*q+1],ww.y,a1);
                    a2=fmaf(xs[4*q+2],ww.z,a2); a3=fmaf(xs[4*q+3],ww.w,a3);
                }
                gs[tid] = (a0+a1)+(a2+a3);
            }
            __syncthreads();
            if (tid < HID){
                float ig=sigf(gs[tid]),        fg=sigf(gs[HID+tid]);
                float gg=tanhf(gs[2*HID+tid]), og=sigf(gs[3*HID+tid]);
                float c2 = fg*c0s[tid] + ig*gg;
                c0s[tid]=c2; h0s[tid]=og*tanhf(c2);
            }
            __syncthreads();
            if (tid >= GSZ){
                const int jj = tid - GSZ;
                float a0 = dbih1[jj]+dbhh1[jj]+hpart, a1=0.f, a2=0.f, a3=0.f;
                const float4* wi4 = (const float4*)(dWih1 + jj*HID);
                #pragma unroll
                for (int q=0;q<8;q++){
                    float4 ww = wi4[q];
                    a0=fmaf(h0s[4*q],ww.x,a0);   a1=fmaf(h0s[4*q+1],ww.y,a1);
                    a2=fmaf(h0s[4*q+2],ww.z,a2); a3=fmaf(h0s[4*q+3],ww.w,a3);
                }
                gs[GSZ+jj] = (a0+a1)+(a2+a3);
            }
            __syncthreads();
            if (tid < HID){
                float ig=sigf(gs[GSZ+tid]),        fg=sigf(gs[GSZ+HID+tid]);
                float gg=tanhf(gs[GSZ+2*HID+tid]), og=sigf(gs[GSZ+3*HID+tid]);
                float c2 = fg*c1s[tid] + ig*gg;
                float h2 = og*tanhf(c2);
                c1s[tid]=c2; h1s[tid]=h2;
                g_h1T[tid*BD + bid] = h2;
            }
            __syncthreads();
            if (tid == 0){
                __threadfence();
                *(volatile unsigned*)&g_hflag[bid] = baseH + (unsigned)t + 1u;
            }
            // precompute Whh·h for next cell (hidden behind logits)
            if (t < NSTEP-1){
                if (tid < GSZ){
                    float a0=0.f,a1=0.f,a2=0.f,a3=0.f;
                    const float4* wh4 = (const float4*)(dWhh0 + tid*HID);
                    #pragma unroll
                    for (int q=0;q<8;q++){
                        float4 ww = wh4[q];
                        a0=fmaf(h0s[4*q],ww.x,a0);   a1=fmaf(h0s[4*q+1],ww.y,a1);
                        a2=fmaf(h0s[4*q+2],ww.z,a2); a3=fmaf(h0s[4*q+3],ww.w,a3);
                    }
                    hpart = (a0+a1)+(a2+a3);
                } else {
                    float a0=0.f,a1=0.f,a2=0.f,a3=0.f;
                    const float4* wh4 = (const float4*)(dWhh1 + (tid-GSZ)*HID);
                    #pragma unroll
                    for (int q=0;q<8;q++){
                        float4 ww = wh4[q];
                        a0=fmaf(h1s[4*q],ww.x,a0);   a1=fmaf(h1s[4*q+1],ww.y,a1);
                        a2=fmaf(h1s[4*q+2],ww.z,a2); a3=fmaf(h1s[4*q+3],ww.w,a3);
                    }
                    hpart = (a0+a1)+(a2+a3);
                }
            }
        }

        // ---------- wait: all 32 h1 columns ready ----------
        if (tid < 32){
            const unsigned tgt = baseH + (unsigned)t + 1u;
            for(;;){
                unsigned f = *((volatile unsigned*)g_hflag + tid);
                if (__all_sync(0xFFFFFFFFu, (int)(f - tgt) >= 0)) break;
            }
            __threadfence();
        }
        __syncthreads();

        // ---------- logits (all blocks) ----------
        {
            const unsigned long long* src = (const unsigned long long*)g_h1T;
            hp[tid]       = __ldcg(src + tid);
            hp[tid + 256] = __ldcg(src + tid + 256);
        }
        cand[tid] = 0ull;
        __syncthreads();

        unsigned long long acc[16];
        if (wact){
            {
                unsigned long long bb = pk2(bias, bias);
                #pragma unroll
                for (int p=0;p<16;p++) acc[p]=bb;
            }
            #pragma unroll
            for (int k=0;k<HID;k++){
                unsigned long long ww = pk2(w[k], w[k]);
                const ulonglong2* hr = (const ulonglong2*)(hp + k*16);
                #pragma unroll
                for (int q=0;q<8;q++){
                    ulonglong2 h2 = hr[q];
                    acc[2*q]   = ffma2(h2.x, ww, acc[2*q]);
                    acc[2*q+1] = ffma2(h2.y, ww, acc[2*q+1]);
                }
            }
            if (valid){
                float* o = out + ((size_t)t*BD)*VOCABN + v;
                #pragma unroll
                for (int p=0;p<16;p++){
                    unsigned long long a = acc[p];
                    o[(size_t)(2*p)*VOCABN]   = __uint_as_float((unsigned)(a & 0xFFFFFFFFull));
                    o[(size_t)(2*p+1)*VOCABN] = __uint_as_float((unsigned)(a >> 32));
                }
            }
        }

        if (t < NSTEP-1){
            // per-warp argmax over this block's rows
            if (wact){
                const unsigned vk = 0xFFFFFFFFu - (unsigned)v;
                #pragma unroll
                for (int b=0;b<BD;b++){
                    unsigned long long a = acc[b>>1];
                    unsigned u = (b&1) ? (unsigned)(a>>32) : (unsigned)(a & 0xFFFFFFFFull);
                    unsigned o_ = valid ? ordb(u) : 0u;
                    unsigned mx = __reduce_max_sync(0xFFFFFFFFu, o_);
                    unsigned ball = __ballot_sync(0xFFFFFFFFu, (o_ == mx) && valid);
                    if (ball){
                        int leader = __ffs(ball) - 1;
                        if (lane == leader)
                            cand[wslot*BD + b] = ((unsigned long long)mx << 32) | (unsigned long long)vk;
                    }
                }
            }
            __syncthreads();
            if (tid < BD){
                unsigned long long m = cand[tid];
                #pragma unroll
                for (int wq=1;wq<6;wq++){
                    unsigned long long k = cand[wq*BD + tid];
                    if (k > m) m = k;
                }
                atomicMax(&g_amax3[t%3][tid], m);
            }
            __syncthreads();
            if (tid == 0){
                __threadfence();
                atomicAdd(&g_arr2, 1u);
            }
        }
    }
}

// ================= launch =================
extern "C" void kernel_launch(void* const* d_in, const int* in_sizes, int n_in,
                              void* d_out, int out_size)
{
    const int*   x_src  = (const int*)  d_in[0];
    const int*   x_tgt  = (const int*)  d_in[1];
    const float* enc_emb= (const float*)d_in[2];
    const float* eWih0  = (const float*)d_in[3];
    const float* eWhh0  = (const float*)d_in[4];
    const float* ebih0  = (const float*)d_in[5];
    const float* ebhh0  = (const float*)d_in[6];
    const float* eWih1  = (const float*)d_in[7];
    const float* eWhh1  = (const float*)d_in[8];
    const float* ebih1  = (const float*)d_in[9];
    const float* ebhh1  = (const float*)d_in[10];
    const float* dec_emb= (const float*)d_in[11];
    const float* dWih0  = (const float*)d_in[12];
    const float* dWhh0  = (const float*)d_in[13];
    const float* dbih0  = (const float*)d_in[14];
    const float* dbhh0  = (const float*)d_in[15];
    const float* dWih1  = (const float*)d_in[16];
    const float* dWhh1  = (const float*)d_in[17];
    const float* dbih1  = (const float*)d_in[18];
    const float* dbhh1  = (const float*)d_in[19];
    const float* fcW    = (const float*)d_in[20];
    const float* fcb    = (const float*)d_in[21];
    float* out = (float*)d_out;

    mega_kernel<<<NB, 256>>>(x_src, x_tgt, enc_emb,
                             eWih0,eWhh0,ebih0,ebhh0,eWih1,eWhh1,ebih1,ebhh1,
                             dec_emb,
                             dWih0,dWhh0,dbih0,dbhh0,dWih1,dWhh1,dbih1,dbhh1,
                             fcW, fcb, out);
}

// round 14
// speedup vs baseline: 1.2765x; 1.2765x over previous
#include <cuda_runtime.h>

#define HID    32
#define EMB    32
#define BD     32
#define VOCABN 50257
#define S_SRC  64
#define NSTEP  63
#define GSZ    (4*HID)     // 128 gate rows per layer
#define NB     296         // 2 blocks per SM
#define RPB    170         // vocab rows per block: 296*170 = 50320 >= 50257

// ---------------- device scratch ----------------
__device__ __align__(16) float g_h1T[HID*BD];          // [k][b] (u64-pair friendly)
__device__ unsigned long long g_part[NB*BD];           // per-block winner keys [bid][b]
__device__ unsigned g_pseq[NB];                        // per-block publish seq (monotonic)
__device__ unsigned g_hcnt;                            // h1-ready counter (monotonic)
__device__ unsigned g_arriveB, g_relB;                 // init barrier

// ---------------- helpers ----------------
__device__ __forceinline__ float sigf(float x){ return 1.f/(1.f+expf(-x)); }

__device__ __forceinline__ unsigned long long pk2(float lo, float hi){
    unsigned long long r;
    asm("mov.b64 %0, {%1, %2};" : "=l"(r) : "f"(lo), "f"(hi));
    return r;
}
__device__ __forceinline__ unsigned long long ffma2(unsigned long long a,
                                                    unsigned long long b,
                                                    unsigned long long c){
    unsigned long long d;
    asm("fma.rn.f32x2 %0, %1, %2, %3;" : "=l"(d) : "l"(a), "l"(b), "l"(c));
    return d;
}
__device__ __forceinline__ unsigned ordb(unsigned u){
    return (u & 0x80000000u) ? ~u : (u | 0x80000000u);
}

// ================= the one persistent kernel =================
__global__ void __launch_bounds__(256, 2) mega_kernel(
    const int* __restrict__ x_src, const int* __restrict__ x_tgt,
    const float* __restrict__ enc_emb,
    const float* __restrict__ eWih0, const float* __restrict__ eWhh0,
    const float* __restrict__ ebih0, const float* __restrict__ ebhh0,
    const float* __restrict__ eWih1, const float* __restrict__ eWhh1,
    const float* __restrict__ ebih1, const float* __restrict__ ebhh1,
    const float* __restrict__ dec_emb,
    const float* __restrict__ dWih0, const float* __restrict__ dWhh0,
    const float* __restrict__ dbih0, const float* __restrict__ dbhh0,
    const float* __restrict__ dWih1, const float* __restrict__ dWhh1,
    const float* __restrict__ dbih1, const float* __restrict__ dbhh1,
    const float* __restrict__ fcW,   const float* __restrict__ fcb,
    float* __restrict__ out)
{
    const int bid = blockIdx.x, tid = threadIdx.x;
    __shared__ float xs[EMB], h0s[HID], c0s[HID], h1s[HID], c1s[HID];
    __shared__ float gs[2*GSZ];
    __shared__ __align__(16) unsigned long long hp[HID*16];
    __shared__ unsigned long long cand[256];
    __shared__ int toks;

    // base snapshots (all counters monotonic across graph replays; every block
    // reads them before the init barrier, and nobody advances them until every
    // block has passed the init barrier)
    const unsigned baseP  = *(volatile unsigned*)&g_pseq[0];
    const unsigned baseHC = *(volatile unsigned*)&g_hcnt;
    const unsigned baseB  = *(volatile unsigned*)&g_relB;

    // ---- initial full grid barrier (replay-safe) ----
    __syncthreads();
    if (tid == 0){
        __threadfence();
        if (atomicAdd(&g_arriveB, 1u) == NB-1u){
            atomicExch(&g_arriveB, 0u);
            __threadfence();
            atomicExch(&g_relB, baseB + 1u);
        } else {
            while ((int)(*(volatile unsigned*)&g_relB - (baseB + 1u)) < 0) {}
        }
    }
    __syncthreads();

    float hpart = 0.f;   // precomputed Whh·h contribution for the next cell
    float cbias = 0.f;   // cached gate bias (cell blocks)

    // ================= encoder (blocks 0..31, one batch each) =================
    if (bid < BD){
        float wi[HID], wh[HID], bias2;
        if (tid < GSZ){
            #pragma unroll
            for (int k=0;k<HID;k++){ wi[k]=eWih0[tid*EMB+k]; wh[k]=eWhh0[tid*HID+k]; }
            bias2 = ebih0[tid] + ebhh0[tid];
        } else {
            const int j = tid - GSZ;
            #pragma unroll
            for (int k=0;k<HID;k++){ wi[k]=eWih1[j*HID+k]; wh[k]=eWhh1[j*HID+k]; }
            bias2 = ebih1[j] + ebhh1[j];
        }
        if (tid < HID){ h0s[tid]=0.f; c0s[tid]=0.f; h1s[tid]=0.f; c1s[tid]=0.f; }
        __syncthreads();

        for (int s=0;s<S_SRC;s++){
            if (tid < EMB) xs[tid] = enc_emb[(size_t)x_src[s*BD+bid]*EMB + tid];
            __syncthreads();
            if (tid < GSZ){
                float a0=bias2, a1=0.f, a2=0.f, a3=0.f;
                #pragma unroll
                for (int k=0;k<HID;k+=4){
                    a0=fmaf(xs[k],wi[k],a0);     a1=fmaf(xs[k+1],wi[k+1],a1);
                    a2=fmaf(xs[k+2],wi[k+2],a2); a3=fmaf(xs[k+3],wi[k+3],a3);
                }
                #pragma unroll
                for (int k=0;k<HID;k+=4){
                    a0=fmaf(h0s[k],wh[k],a0);     a1=fmaf(h0s[k+1],wh[k+1],a1);
                    a2=fmaf(h0s[k+2],wh[k+2],a2); a3=fmaf(h0s[k+3],wh[k+3],a3);
                }
                gs[tid] = (a0+a1)+(a2+a3);
            }
            __syncthreads();
            if (tid < HID){
                float ig=sigf(gs[tid]),        fg=sigf(gs[HID+tid]);
                float gg=tanhf(gs[2*HID+tid]), og=sigf(gs[3*HID+tid]);
                float c2 = fg*c0s[tid] + ig*gg;
                c0s[tid]=c2; h0s[tid]=og*tanhf(c2);
            }
            __syncthreads();
            if (tid >= GSZ){
                float a0=bias2, a1=0.f, a2=0.f, a3=0.f;
                #pragma unroll
                for (int k=0;k<HID;k+=4){
                    a0=fmaf(h0s[k],wi[k],a0);     a1=fmaf(h0s[k+1],wi[k+1],a1);
                    a2=fmaf(h0s[k+2],wi[k+2],a2); a3=fmaf(h0s[k+3],wi[k+3],a3);
                }
                #pragma unroll
                for (int k=0;k<HID;k+=4){
                    a0=fmaf(h1s[k],wh[k],a0);     a1=fmaf(h1s[k+1],wh[k+1],a1);
                    a2=fmaf(h1s[k+2],wh[k+2],a2); a3=fmaf(h1s[k+3],wh[k+3],a3);
                }
                gs[GSZ + (tid-GSZ)] = (a0+a1)+(a2+a3);
            }
            __syncthreads();
            if (tid < HID){
                float ig=sigf(gs[GSZ+tid]),        fg=sigf(gs[GSZ+HID+tid]);
                float gg=tanhf(gs[GSZ+2*HID+tid]), og=sigf(gs[GSZ+3*HID+tid]);
                float c2 = fg*c1s[tid] + ig*gg;
                c1s[tid]=c2; h1s[tid]=og*tanhf(c2);
            }
            __syncthreads();
        }
        // cached decoder bias + Whh·h precompute for cell(0)
        if (tid < GSZ){
            cbias = dbih0[tid]+dbhh0[tid];
            float a0=0.f,a1=0.f,a2=0.f,a3=0.f;
            const float4* wh4 = (const float4*)(dWhh0 + tid*HID);
            #pragma unroll
            for (int q=0;q<8;q++){
                float4 ww = wh4[q];
                a0=fmaf(h0s[4*q],ww.x,a0);   a1=fmaf(h0s[4*q+1],ww.y,a1);
                a2=fmaf(h0s[4*q+2],ww.z,a2); a3=fmaf(h0s[4*q+3],ww.w,a3);
            }
            hpart = (a0+a1)+(a2+a3);
        } else {
            cbias = dbih1[tid-GSZ]+dbhh1[tid-GSZ];
            float a0=0.f,a1=0.f,a2=0.f,a3=0.f;
            const float4* wh4 = (const float4*)(dWhh1 + (tid-GSZ)*HID);
            #pragma unroll
            for (int q=0;q<8;q++){
                float4 ww = wh4[q];
                a0=fmaf(h1s[4*q],ww.x,a0);   a1=fmaf(h1s[4*q+1],ww.y,a1);
                a2=fmaf(h1s[4*q+2],ww.z,a2); a3=fmaf(h1s[4*q+3],ww.w,a3);
            }
            hpart = (a0+a1)+(a2+a3);
        }
    }

    // ================= persistent fc weights, SMSP-balanced warp mapping =================
    const int sel  = (bid >= NB/2) ? 1 : 0;
    const int w8   = tid >> 5, lane = tid & 31;
    const bool wact = sel ? ((w8 < 4) || (w8 >= 6)) : (w8 < 6);
    const int wslot = sel ? ((w8 < 4) ? w8 : (w8 - 2)) : w8;
    const int j    = wslot*32 + lane;                 // 0..191
    const int v    = bid*RPB + j;
    const bool valid = wact && (j < RPB) && (v < VOCABN);
    const int vc   = valid ? v : (VOCABN-1);

    float w[HID];
    {
        const float4* w4 = (const float4*)(fcW + (size_t)vc*HID);
        #pragma unroll
        for (int q=0;q<8;q++){
            float4 t4 = w4[q];
            w[4*q]=t4.x; w[4*q+1]=t4.y; w[4*q+2]=t4.z; w[4*q+3]=t4.w;
        }
    }
    const float bias = fcb[vc];

    // ================= decoder loop =================
    for (int t=0;t<NSTEP;t++){
        // ---------- cell (blocks 0..31) ----------
        if (bid < BD){
            if (t == 0){
                if (tid == 0) toks = x_tgt[bid];
            } else {
                // wait for all 296 step-(t-1) winner publications, then scan column bid
                const unsigned tgt = baseP + (unsigned)t;
                unsigned long long m;
                {
                    volatile unsigned* ps = (volatile unsigned*)g_pseq;
                    const bool two = tid < (NB-256);
                    for(;;){
                        unsigned f0 = ps[tid];
                        unsigned f1 = two ? ps[tid+256] : tgt;
                        if ((int)(f0-tgt) >= 0 && (int)(f1-tgt) >= 0) break;
                    }
                    __threadfence();
                    m = __ldcg(&g_part[tid*BD + bid]);
                    if (two){
                        unsigned long long k2 = __ldcg(&g_part[(tid+256)*BD + bid]);
                        if (k2 > m) m = k2;
                    }
                }
                #pragma unroll
                for (int off=16; off; off>>=1){
                    unsigned long long o2 = __shfl_down_sync(0xFFFFFFFFu, m, off);
                    if (o2 > m) m = o2;
                }
                if ((tid & 31) == 0) cand[tid>>5] = m;
                __syncthreads();
                if (tid == 0){
                    unsigned long long mm = cand[0];
                    #pragma unroll
                    for (int i=1;i<8;i++) if (cand[i] > mm) mm = cand[i];
                    toks = (int)(0xFFFFFFFFu - (unsigned)(mm & 0xFFFFFFFFull));
                }
            }
            __syncthreads();
            if (tid < EMB) xs[tid] = dec_emb[(size_t)toks*EMB + tid];
            __syncthreads();

            if (tid < GSZ){
                float a0 = cbias+hpart, a1=0.f, a2=0.f, a3=0.f;
                const float4* wi4 = (const float4*)(dWih0 + tid*EMB);
                #pragma unroll
                for (int q=0;q<8;q++){
                    float4 ww = wi4[q];
                    a0=fmaf(xs[4*q],ww.x,a0);   a1=fmaf(xs[4*q+1],ww.y,a1);
                    a2=fmaf(xs[4*q+2],ww.z,a2); a3=fmaf(xs[4*q+3],ww.w,a3);
                }
                gs[tid] = (a0+a1)+(a2+a3);
            }
            __syncthreads();
            if (tid < HID){
                float ig=sigf(gs[tid]),        fg=sigf(gs[HID+tid]);
                float gg=tanhf(gs[2*HID+tid]), og=sigf(gs[3*HID+tid]);
                float c2 = fg*c0s[tid] + ig*gg;
                c0s[tid]=c2; h0s[tid]=og*tanhf(c2);
            }
            __syncthreads();
            if (tid >= GSZ){
                const int jj = tid - GSZ;
                float a0 = cbias+hpart, a1=0.f, a2=0.f, a3=0.f;
                const float4* wi4 = (const float4*)(dWih1 + jj*HID);
                #pragma unroll
                for (int q=0;q<8;q++){
                    float4 ww = wi4[q];
                    a0=fmaf(h0s[4*q],ww.x,a0);   a1=fmaf(h0s[4*q+1],ww.y,a1);
                    a2=fmaf(h0s[4*q+2],ww.z,a2); a3=fmaf(h0s[4*q+3],ww.w,a3);
                }
                gs[GSZ+jj] = (a0+a1)+(a2+a3);
            }
            __syncthreads();
            if (tid < HID){
                float ig=sigf(gs[GSZ+tid]),        fg=sigf(gs[GSZ+HID+tid]);
                float gg=tanhf(gs[GSZ+2*HID+tid]), og=sigf(gs[GSZ+3*HID+tid]);
                float c2 = fg*c1s[tid] + ig*gg;
                float h2 = og*tanhf(c2);
                c1s[tid]=c2; h1s[tid]=h2;
                g_h1T[tid*BD + bid] = h2;
            }
            __syncthreads();
            if (tid == 0){
                __threadfence();
                atomicAdd(&g_hcnt, 1u);
            }
            // precompute Whh·h for next cell (hidden behind logits phase)
            if (t < NSTEP-1){
                if (tid < GSZ){
                    float a0=0.f,a1=0.f,a2=0.f,a3=0.f;
                    const float4* wh4 = (const float4*)(dWhh0 + tid*HID);
                    #pragma unroll
                    for (int q=0;q<8;q++){
                        float4 ww = wh4[q];
                        a0=fmaf(h0s[4*q],ww.x,a0);   a1=fmaf(h0s[4*q+1],ww.y,a1);
                        a2=fmaf(h0s[4*q+2],ww.z,a2); a3=fmaf(h0s[4*q+3],ww.w,a3);
                    }
                    hpart = (a0+a1)+(a2+a3);
                } else {
                    float a0=0.f,a1=0.f,a2=0.f,a3=0.f;
                    const float4* wh4 = (const float4*)(dWhh1 + (tid-GSZ)*HID);
                    #pragma unroll
                    for (int q=0;q<8;q++){
                        float4 ww = wh4[q];
                        a0=fmaf(h1s[4*q],ww.x,a0);   a1=fmaf(h1s[4*q+1],ww.y,a1);
                        a2=fmaf(h1s[4*q+2],ww.z,a2); a3=fmaf(h1s[4*q+3],ww.w,a3);
                    }
                    hpart = (a0+a1)+(a2+a3);
                }
            }
        }

        // ---------- wait: all 32 h1 columns ready ----------
        if (tid == 0){
            const unsigned tgt = baseHC + 32u*(unsigned)(t+1);
            while ((int)(*(volatile unsigned*)&g_hcnt - tgt) < 0) {}
            __threadfence();
        }
        __syncthreads();

        // ---------- logits (all blocks) ----------
        {
            const unsigned long long* src = (const unsigned long long*)g_h1T;
            hp[tid]       = __ldcg(src + tid);
            hp[tid + 256] = __ldcg(src + tid + 256);
        }
        cand[tid] = 0ull;
        __syncthreads();

        unsigned long long acc[16];
        if (wact){
            {
                unsigned long long bb = pk2(bias, bias);
                #pragma unroll
                for (int p=0;p<16;p++) acc[p]=bb;
            }
            #pragma unroll
            for (int k=0;k<HID;k++){
                unsigned long long ww = pk2(w[k], w[k]);
                const ulonglong2* hr = (const ulonglong2*)(hp + k*16);
                #pragma unroll
                for (int q=0;q<8;q++){
                    ulonglong2 h2 = hr[q];
                    acc[2*q]   = ffma2(h2.x, ww, acc[2*q]);
                    acc[2*q+1] = ffma2(h2.y, ww, acc[2*q+1]);
                }
            }
        }

        if (t < NSTEP-1){
            // per-warp argmax over this block's rows (publish BEFORE out writes)
            if (wact){
                const unsigned vk = 0xFFFFFFFFu - (unsigned)v;
                #pragma unroll
                for (int b=0;b<BD;b++){
                    unsigned long long a = acc[b>>1];
                    unsigned u = (b&1) ? (unsigned)(a>>32) : (unsigned)(a & 0xFFFFFFFFull);
                    unsigned o_ = valid ? ordb(u) : 0u;
                    unsigned mx = __reduce_max_sync(0xFFFFFFFFu, o_);
                    unsigned ball = __ballot_sync(0xFFFFFFFFu, (o_ == mx) && valid);
                    if (ball){
                        int leader = __ffs(ball) - 1;
                        if (lane == leader)
                            cand[wslot*BD + b] = ((unsigned long long)mx << 32) | (unsigned long long)vk;
                    }
                }
            }
            __syncthreads();
            if (tid < BD){
                unsigned long long m = cand[tid];
                #pragma unroll
                for (int wq=1;wq<6;wq++){
                    unsigned long long k = cand[wq*BD + tid];
                    if (k > m) m = k;
                }
                g_part[bid*BD + tid] = m;          // plain store, zero contention
            }
            __syncthreads();
            if (tid == 0){
                __threadfence();
                *(volatile unsigned*)&g_pseq[bid] = baseP + (unsigned)t + 1u;
            }
        }

        // output writes — off the critical path
        if (valid){
            float* o = out + ((size_t)t*BD)*VOCABN + v;
            #pragma unroll
            for (int p=0;p<16;p++){
                unsigned long long a = acc[p];
                o[(size_t)(2*p)*VOCABN]   = __uint_as_float((unsigned)(a & 0xFFFFFFFFull));
                o[(size_t)(2*p+1)*VOCABN] = __uint_as_float((unsigned)(a >> 32));
            }
        }
    }
}

// ================= launch =================
extern "C" void kernel_launch(void* const* d_in, const int* in_sizes, int n_in,
                              void* d_out, int out_size)
{
    const int*   x_src  = (const int*)  d_in[0];
    const int*   x_tgt  = (const int*)  d_in[1];
    const float* enc_emb= (const float*)d_in[2];
    const float* eWih0  = (const float*)d_in[3];
    const float* eWhh0  = (const float*)d_in[4];
    const float* ebih0  = (const float*)d_in[5];
    const float* ebhh0  = (const float*)d_in[6];
    const float* eWih1  = (const float*)d_in[7];
    const float* eWhh1  = (const float*)d_in[8];
    const float* ebih1  = (const float*)d_in[9];
    const float* ebhh1  = (const float*)d_in[10];
    const float* dec_emb= (const float*)d_in[11];
    const float* dWih0  = (const float*)d_in[12];
    const float* dWhh0  = (const float*)d_in[13];
    const float* dbih0  = (const float*)d_in[14];
    const float* dbhh0  = (const float*)d_in[15];
    const float* dWih1  = (const float*)d_in[16];
    const float* dWhh1  = (const float*)d_in[17];
    const float* dbih1  = (const float*)d_in[18];
    const float* dbhh1  = (const float*)d_in[19];
    const float* fcW    = (const float*)d_in[20];
    const float* fcb    = (const float*)d_in[21];
    float* out = (float*)d_out;

    mega_kernel<<<NB, 256>>>(x_src, x_tgt, enc_emb,
                             eWih0,eWhh0,ebih0,ebhh0,eWih1,eWhh1,ebih1,ebhh1,
                             dec_emb,
                             dWih0,dWhh0,dbih0,dbhh0,dWih1,dWhh1,dbih1,dbhh1,
                             fcW, fcb, out);
}